// round 12
// baseline (speedup 1.0000x reference)
#include <cuda_runtime.h>
#include <cuda_fp16.h>

#define NN 5
#define BB 8
#define CC 256
#define HWD 1024
#define NCH 8             // 0-3: main fp16 (k64 each), 4-7: corr int8 (k'128 each)
#define TM 64
#define TPX 32
#define THREADS 256
#define NSTG 3
#define LSCALE 2048.0f
// corr combine: (q_Mhi * q_xlo_s) uses scales 254 & 31.75 -> product x8064.5; /2048 for lo-scale
#define K2F (1.0f / (8064.5f * 2048.0f))

// fp16 hi operands (K=256), k-contiguous
__device__ __align__(16) __half g_Ahm[NN * CC * 256];
__device__ __align__(16) __half g_Ahw[NN * CC * 256];
__device__ __align__(16) __half g_Xh [NN * BB * HWD * 256];
// int8 corr operands (K'=512): A=[q(Mhi)|q(Mlo*2^11)], B=[q(xlo*2^11)|q(xhi)]
__device__ __align__(16) char g_A8m[NN * CC * 512];
__device__ __align__(16) char g_A8w[NN * CC * 512];
__device__ __align__(16) char g_X8 [NN * BB * HWD * 512];

__device__ __forceinline__ char q8(float v, float s) {
    float t = fminf(fmaxf(v * s, -127.f), 127.f);
    return (char)__float2int_rn(t);
}

__global__ void prep_w(const float* __restrict__ w) {
    int idx = blockIdx.x * blockDim.x + threadIdx.x;   // (i*CC+o)*CC + k
    if (idx >= NN * CC * CC) return;
    int k = idx & 255;
    int oi = idx >> 8;
    int o = oi & 255, i = oi >> 8;
    const float* row = w + (size_t)(i * CC + o) * (2 * CC);
    float w2 = row[CC + k];
    float m  = row[k] + w2;
    __half mh = __float2half_rn(m), wh = __float2half_rn(w2);
    float mhf = __half2float(mh), whf = __half2float(wh);
    size_t bh = (size_t)(i * CC + o) * 256 + k;
    g_Ahm[bh] = mh;  g_Ahw[bh] = wh;
    size_t b8 = (size_t)(i * CC + o) * 512;
    g_A8m[b8 + k]       = q8(mhf, 254.0f);                       // /0.5
    g_A8m[b8 + 256 + k] = q8((m  - mhf) * LSCALE, 508.0f);       // /0.25
    g_A8w[b8 + k]       = q8(whf, 254.0f);
    g_A8w[b8 + 256 + k] = q8((w2 - whf) * LSCALE, 508.0f);
}

// Transpose [k][p] -> [p][k] + hi/lo split + int8 quant, via smem tile (32k x 128p).
__global__ __launch_bounds__(256) void prep_x(const float* __restrict__ x) {
    __shared__ float s[32][129];
    int bid = blockIdx.x;                      // jb(40) * ktile(8) * ptile(8)
    int pt = bid & 7, kt = (bid >> 3) & 7, jb = bid >> 6;
    int k0 = kt * 32, p0 = pt * 128;
    int tid = threadIdx.x;
    #pragma unroll
    for (int t = 0; t < 16; t++) {
        int idx = tid + t * 256;
        int kk = idx >> 7, pp = idx & 127;
        s[kk][pp] = x[((size_t)jb * CC + k0 + kk) * HWD + p0 + pp];
    }
    __syncthreads();
    int pp = tid & 127, kh = tid >> 7;         // kh: 16-k half of the 32
    __half  hbuf[16];
    char    lobuf[16], hibuf[16];
    #pragma unroll
    for (int kk = 0; kk < 16; kk++) {
        float v = s[kh * 16 + kk][pp];
        __half h = __float2half_rn(v);
        float hf = __half2float(h);
        hbuf[kk]  = h;
        lobuf[kk] = q8((v - hf) * LSCALE, 31.75f);   // /4
        hibuf[kk] = q8(hf, 15.875f);                 // /8
    }
    size_t ph = (size_t)(jb * HWD + p0 + pp);
    __half* dh = g_Xh + ph * 256 + k0 + kh * 16;
    *(uint4*)dh       = *(uint4*)hbuf;
    *(uint4*)(dh + 8) = *(uint4*)(hbuf + 8);
    char* d8 = g_X8 + ph * 512;
    *(uint4*)(d8 + k0 + kh * 16)       = *(uint4*)lobuf;
    *(uint4*)(d8 + 256 + k0 + kh * 16) = *(uint4*)hibuf;
}

// ---- smem stage: A_M 8K | A_W 8K | B[5] 20K = 36KB; 3 stages = 108KB ----
#define STG 36864
#define OFF_AW 8192
#define OFF_B 16384
struct SmemT { char st[NSTG][STG]; };

#define LDM4(r, a) \
    asm volatile("ldmatrix.sync.aligned.m8n8.x4.shared.b16 {%0,%1,%2,%3}, [%4];" \
        : "=r"((r)[0]), "=r"((r)[1]), "=r"((r)[2]), "=r"((r)[3]) : "r"(a))

#define MMA32(d, a, b0, b1) \
    asm volatile("mma.sync.aligned.m16n8k16.row.col.f32.f16.f16.f32 " \
        "{%0,%1,%2,%3}, {%4,%5,%6,%7}, {%8,%9}, {%0,%1,%2,%3};" \
        : "+f"((d)[0]), "+f"((d)[1]), "+f"((d)[2]), "+f"((d)[3]) \
        : "r"((a)[0]), "r"((a)[1]), "r"((a)[2]), "r"((a)[3]), "r"(b0), "r"(b1))

#define MMA8(d, a, b0, b1) \
    asm volatile("mma.sync.aligned.m16n8k32.row.col.s32.s8.s8.s32 " \
        "{%0,%1,%2,%3}, {%4,%5,%6,%7}, {%8,%9}, {%0,%1,%2,%3};" \
        : "+r"((d)[0]), "+r"((d)[1]), "+r"((d)[2]), "+r"((d)[3]) \
        : "r"((a)[0]), "r"((a)[1]), "r"((a)[2]), "r"((a)[3]), "r"(b0), "r"(b1))

__global__ __launch_bounds__(THREADS, 2) void fused_kernel(
    const float* __restrict__ x,
    const float* __restrict__ bias,
    float* __restrict__ out)
{
    extern __shared__ __align__(16) char smem_raw[];
    SmemT& sm = *reinterpret_cast<SmemT*>(smem_raw);

    const int i  = blockIdx.z;
    const int o0 = blockIdx.y * TM;
    const int b  = blockIdx.x >> 5;
    const int p0 = (blockIdx.x & 31) * TPX;

    const int tid  = threadIdx.x;
    const int lane = tid & 31;
    const int wid  = tid >> 5;
    const int wo = (wid >> 1) * 16;            // warp o offset (0,16,32,48)
    const int wn = (wid & 1) * 16;             // warp px offset (0,16)
    const unsigned smem_base = (unsigned)__cvta_generic_to_shared(&sm);

    // ldmatrix geometry: 128B rows for every tile; window = kstep*32 bytes
    const int sw7  = (lane & 7) << 4;
    const int arow = wo + ((lane >> 3) & 1) * 8 + (lane & 7);
    const int a16  = (lane >> 4) * 16;
    const int brow = wn + (lane >> 4) * 8 + (lane & 7);
    const int b16  = ((lane >> 3) & 1) * 16;

    float acc[6][2][4];
    int   accC[6][2][4];
    #pragma unroll
    for (int m = 0; m < 6; m++)
        #pragma unroll
        for (int g = 0; g < 2; g++)
            #pragma unroll
            for (int e = 0; e < 4; e++) { acc[m][g][e] = 0.f; accC[m][g][e] = 0; }

    auto load_chunk = [&](int c, int s) {
        char* stg = sm.st[s];
        const bool mn = (c < 4);
        const int ka = mn ? c * 64 : (c - 4) * 128;   // halves (main) / bytes (corr)
        #pragma unroll
        for (int t = 0; t < 9; t++) {
            int q = tid + t * THREADS;                // 2304 x 16B
            const char* src;
            int doff;
            if (q < 1024) {                           // A tiles: 2 mats x 64row x 128B
                int mat = q >> 9, idx = q & 511, row = idx >> 3, c16 = idx & 7;
                if (mn) {
                    const __half* g = mat ? g_Ahw : g_Ahm;
                    src = (const char*)(g + (size_t)(i * CC + o0 + row) * 256 + ka + c16 * 8);
                } else {
                    const char* g = mat ? g_A8w : g_A8m;
                    src = g + (size_t)(i * CC + o0 + row) * 512 + ka + c16 * 16;
                }
                doff = mat * OFF_AW + row * 128 + ((c16 << 4) ^ ((row & 7) << 4));
            } else {                                  // B tiles: 5 x 32row x 128B
                int q2 = q - 1024;
                int j = q2 >> 8, idx = q2 & 255, row = idx >> 3, c16 = idx & 7;
                size_t pb = (size_t)((j * BB + b) * HWD + p0 + row);
                if (mn) src = (const char*)(g_Xh + pb * 256 + ka + c16 * 8);
                else    src = g_X8 + pb * 512 + ka + c16 * 16;
                doff = OFF_B + j * 4096 + row * 128 + ((c16 << 4) ^ ((row & 7) << 4));
            }
            unsigned ds = (unsigned)__cvta_generic_to_shared(stg + doff);
            asm volatile("cp.async.cg.shared.global [%0], [%1], 16;"
                         :: "r"(ds), "l"(src));
        }
        asm volatile("cp.async.commit_group;");
    };

    load_chunk(0, 0);
    load_chunk(1, 1);

    int stage = 0;
    for (int c = 0; c < NCH; c++) {
        asm volatile("cp.async.wait_group 1;");
        __syncthreads();
        if (c + 2 < NCH) {
            int s2 = stage + 2; if (s2 >= NSTG) s2 -= NSTG;
            load_chunk(c + 2, s2);
        }
        const unsigned stq = smem_base + (unsigned)(stage * STG);
        const bool mn = (c < 4);

        #pragma unroll
        for (int st4 = 0; st4 < 4; st4++) {
            const int kko = st4 * 32;                 // 32B window both modes
            unsigned aM[4], aW[4];
            {
                unsigned aa = stq + arow * 128 + (unsigned)((kko + a16) ^ sw7);
                LDM4(aM, aa);
                LDM4(aW, aa + OFF_AW);
            }
            unsigned bf[5][4];
            #pragma unroll
            for (int j = 0; j < NN; j++) {
                unsigned bb0 = stq + OFF_B + j * 4096 + brow * 128
                             + (unsigned)((kko + b16) ^ sw7);
                LDM4(bf[j], bb0);
            }
            if (mn) {
                #pragma unroll
                for (int j = 0; j < NN; j++) {
                    MMA32(acc[j][0], aM, bf[j][0], bf[j][1]);
                    MMA32(acc[j][1], aM, bf[j][2], bf[j][3]);
                    if (j == i) {
                        MMA32(acc[5][0], aW, bf[j][0], bf[j][1]);
                        MMA32(acc[5][1], aW, bf[j][2], bf[j][3]);
                    }
                }
            } else {
                #pragma unroll
                for (int j = 0; j < NN; j++) {
                    MMA8(accC[j][0], aM, bf[j][0], bf[j][1]);
                    MMA8(accC[j][1], aM, bf[j][2], bf[j][3]);
                    if (j == i) {
                        MMA8(accC[5][0], aW, bf[j][0], bf[j][1]);
                        MMA8(accC[5][1], aW, bf[j][2], bf[j][3]);
                    }
                }
            }
        }
        if (++stage == NSTG) stage = 0;
    }

    // ---- fused epilogue: t = main + corr*K2F + bias; edge/softmax/aggregate ----
    const int tq = lane >> 2, tr = lane & 3;
    #pragma unroll
    for (int rh = 0; rh < 2; rh++) {
        const int o = o0 + wo + rh * 8 + tq;
        const float bv = bias[i * CC + o];
        #pragma unroll
        for (int g = 0; g < 2; g++) {
            const int p = p0 + wn + g * 8 + tr * 2;
            float2 xj[NN];
            #pragma unroll
            for (int j = 0; j < NN; j++)
                xj[j] = *(const float2*)(
                    x + ((size_t)((j * BB + b) * CC + o)) * HWD + p);
            float res[2];
            #pragma unroll
            for (int e = 0; e < 2; e++) {
                const int ix = rh * 2 + e;
                const float u = acc[5][g][ix] + (float)accC[5][g][ix] * K2F + bv;
                float ed[NN], m2 = 0.f;
                #pragma unroll
                for (int j = 0; j < NN; j++) {
                    float xv = e ? xj[j].y : xj[j].x;
                    float t = acc[j][g][ix] + (float)accC[j][g][ix] * K2F + u;
                    float d = fabsf(xv - t);
                    ed[j] = (d > 0.3f) ? d : 0.f;
                    m2 = fmaxf(m2, ed[j]);
                }
                float sden = 0.f, a = 0.f;
                #pragma unroll
                for (int j = 0; j < NN; j++) {
                    float wgt = __expf(ed[j] - m2);
                    sden += wgt;
                    a = fmaf(wgt, e ? xj[j].y : xj[j].x, a);
                }
                res[e] = a / sden;
            }
            *(float2*)(out + ((size_t)((i * BB + b) * CC + o)) * HWD + p) =
                make_float2(res[0], res[1]);
        }
    }
}

extern "C" void kernel_launch(void* const* d_in, const int* in_sizes, int n_in,
                              void* d_out, int out_size) {
    const float* x    = (const float*)d_in[0];   // [5,8,256,32,32]
    const float* w    = (const float*)d_in[1];   // [5,256,512]
    const float* bias = (const float*)d_in[2];   // [5,256]
    float* out = (float*)d_out;                  // [5,8,256,32,32]

    cudaFuncSetAttribute(fused_kernel,
                         cudaFuncAttributeMaxDynamicSharedMemorySize,
                         (int)sizeof(SmemT));

    prep_w<<<(NN * CC * CC + 255) / 256, 256>>>(w);
    prep_x<<<NN * BB * 8 * 8, 256>>>(x);
    // grid: x = b(8)*ptile(32) = 256, y = o-tiles(4), z = i(5)
    fused_kernel<<<dim3(256, 4, 5), THREADS, sizeof(SmemT)>>>(x, bias, out);
}

// round 16
// speedup vs baseline: 1.0145x; 1.0145x over previous
#include <cuda_runtime.h>
#include <cuda_fp16.h>

#define NN 5
#define BB 8
#define CC 256
#define HWD 1024
#define NCH 8             // 0-3: main fp16 f32acc (k64 each), 4-7: corr int8 (128B K' each)
#define TM 64
#define TPX 64
#define THREADS 512
#define NSTG 3
#define LSCALE 2048.0f
// corr combine: scales 254*31.75 == 508*15.875 == 8064.5; /2048 for the lo pre-scale
#define K2F (1.0f / (8064.5f * 2048.0f))

// fp16 hi operands (K=256), k-contiguous
__device__ __align__(16) __half g_Ahm[NN * CC * 256];
__device__ __align__(16) __half g_Ahw[NN * CC * 256];
__device__ __align__(16) __half g_Xh [NN * BB * HWD * 256];
// int8 corr operands (K'=512): A=[q(Mhi)|q(Mlo*2^11)], B=[q(xlo*2^11)|q(xhi)]
__device__ __align__(16) char g_A8m[NN * CC * 512];
__device__ __align__(16) char g_A8w[NN * CC * 512];
__device__ __align__(16) char g_X8 [NN * BB * HWD * 512];

__device__ __forceinline__ char q8(float v, float s) {
    float t = fminf(fmaxf(v * s, -127.f), 127.f);
    return (char)__float2int_rn(t);
}

__global__ void prep_w(const float* __restrict__ w) {
    int idx = blockIdx.x * blockDim.x + threadIdx.x;   // (i*CC+o)*CC + k
    if (idx >= NN * CC * CC) return;
    int k = idx & 255;
    int oi = idx >> 8;
    int o = oi & 255, i = oi >> 8;
    const float* row = w + (size_t)(i * CC + o) * (2 * CC);
    float w2 = row[CC + k];
    float m  = row[k] + w2;
    __half mh = __float2half_rn(m), wh = __float2half_rn(w2);
    float mhf = __half2float(mh), whf = __half2float(wh);
    size_t bh = (size_t)(i * CC + o) * 256 + k;
    g_Ahm[bh] = mh;  g_Ahw[bh] = wh;
    size_t b8 = (size_t)(i * CC + o) * 512;
    g_A8m[b8 + k]       = q8(mhf, 254.0f);
    g_A8m[b8 + 256 + k] = q8((m  - mhf) * LSCALE, 508.0f);
    g_A8w[b8 + k]       = q8(whf, 254.0f);
    g_A8w[b8 + 256 + k] = q8((w2 - whf) * LSCALE, 508.0f);
}

// Transpose [k][p] -> [p][k] + hi/lo split + int8 quant, via smem tile (32k x 128p).
__global__ __launch_bounds__(256) void prep_x(const float* __restrict__ x) {
    __shared__ float s[32][129];
    int bid = blockIdx.x;                      // jb(40) * ktile(8) * ptile(8)
    int pt = bid & 7, kt = (bid >> 3) & 7, jb = bid >> 6;
    int k0 = kt * 32, p0 = pt * 128;
    int tid = threadIdx.x;
    #pragma unroll
    for (int t = 0; t < 16; t++) {
        int idx = tid + t * 256;
        int kk = idx >> 7, pp = idx & 127;
        s[kk][pp] = x[((size_t)jb * CC + k0 + kk) * HWD + p0 + pp];
    }
    __syncthreads();
    int pp = tid & 127, kh = tid >> 7;         // kh: which 16-k half of the 32
    __half  hbuf[16];
    char    lobuf[16], hibuf[16];
    #pragma unroll
    for (int kk = 0; kk < 16; kk++) {
        float v = s[kh * 16 + kk][pp];
        __half h = __float2half_rn(v);
        float hf = __half2float(h);
        hbuf[kk]  = h;
        lobuf[kk] = q8((v - hf) * LSCALE, 31.75f);
        hibuf[kk] = q8(hf, 15.875f);
    }
    size_t ph = (size_t)(jb * HWD + p0 + pp);
    __half* dh = g_Xh + ph * 256 + k0 + kh * 16;
    *(uint4*)dh       = *(uint4*)hbuf;
    *(uint4*)(dh + 8) = *(uint4*)(hbuf + 8);
    char* d8 = g_X8 + ph * 512;
    *(uint4*)(d8 + k0 + kh * 16)       = *(uint4*)lobuf;
    *(uint4*)(d8 + 256 + k0 + kh * 16) = *(uint4*)hibuf;
}

// ---- smem stage: A_M 8K | A_W 8K | B[5] 40K = 56KB; 3 stages = 168KB ----
#define STG 57344
#define OFF_AW 8192
#define OFF_B 16384
struct SmemT { char st[NSTG][STG]; };

#define LDM4(r, a) \
    asm volatile("ldmatrix.sync.aligned.m8n8.x4.shared.b16 {%0,%1,%2,%3}, [%4];" \
        : "=r"((r)[0]), "=r"((r)[1]), "=r"((r)[2]), "=r"((r)[3]) : "r"(a))

#define MMA32(d, a, b0, b1) \
    asm volatile("mma.sync.aligned.m16n8k16.row.col.f32.f16.f16.f32 " \
        "{%0,%1,%2,%3}, {%4,%5,%6,%7}, {%8,%9}, {%0,%1,%2,%3};" \
        : "+f"((d)[0]), "+f"((d)[1]), "+f"((d)[2]), "+f"((d)[3]) \
        : "r"((a)[0]), "r"((a)[1]), "r"((a)[2]), "r"((a)[3]), "r"(b0), "r"(b1))

#define MMA8(d, a, b0, b1) \
    asm volatile("mma.sync.aligned.m16n8k32.row.col.s32.s8.s8.s32 " \
        "{%0,%1,%2,%3}, {%4,%5,%6,%7}, {%8,%9}, {%0,%1,%2,%3};" \
        : "+r"((d)[0]), "+r"((d)[1]), "+r"((d)[2]), "+r"((d)[3]) \
        : "r"((a)[0]), "r"((a)[1]), "r"((a)[2]), "r"((a)[3]), "r"(b0), "r"(b1))

__global__ __launch_bounds__(THREADS, 1) void fused_kernel(
    const float* __restrict__ x,
    const float* __restrict__ bias,
    float* __restrict__ out)
{
    extern __shared__ __align__(16) char smem_raw[];
    SmemT& sm = *reinterpret_cast<SmemT*>(smem_raw);

    const int i  = blockIdx.z;
    const int o0 = blockIdx.y * TM;
    const int b  = blockIdx.x >> 4;
    const int p0 = (blockIdx.x & 15) * TPX;

    const int tid  = threadIdx.x;
    const int lane = tid & 31;
    const int wid  = tid >> 5;
    const int wo = (wid >> 2) * 16;            // warp o offset (0,16,32,48)
    const int wn = (wid & 3) * 16;             // warp px offset (0,16,32,48)
    const unsigned smem_base = (unsigned)__cvta_generic_to_shared(&sm);

    const int sw7  = (lane & 7) << 4;
    const int arow = wo + ((lane >> 3) & 1) * 8 + (lane & 7);
    const int a16  = (lane >> 4) * 16;
    const int brow = wn + (lane >> 4) * 8 + (lane & 7);
    const int b16  = ((lane >> 3) & 1) * 16;

    float acc[6][2][4];
    int   accC[6][2][4];
    #pragma unroll
    for (int m = 0; m < 6; m++)
        #pragma unroll
        for (int g = 0; g < 2; g++)
            #pragma unroll
            for (int e = 0; e < 4; e++) { acc[m][g][e] = 0.f; accC[m][g][e] = 0; }

    auto load_chunk = [&](int c, int s) {
        char* stg = sm.st[s];
        const bool mn = (c < 4);
        const int ka = mn ? c * 64 : (c - 4) * 128;   // halves (main) / bytes (corr)
        #pragma unroll
        for (int t = 0; t < 7; t++) {
            int q = tid + t * THREADS;                // 3584 x 16B
            const char* src;
            int doff;
            if (q < 1024) {                           // A tiles: 2 mats x 64row x 128B
                int mat = q >> 9, idx = q & 511, row = idx >> 3, c16 = idx & 7;
                if (mn) {
                    const __half* g = mat ? g_Ahw : g_Ahm;
                    src = (const char*)(g + (size_t)(i * CC + o0 + row) * 256 + ka + c16 * 8);
                } else {
                    const char* g = mat ? g_A8w : g_A8m;
                    src = g + (size_t)(i * CC + o0 + row) * 512 + ka + c16 * 16;
                }
                doff = mat * OFF_AW + row * 128 + ((c16 << 4) ^ ((row & 7) << 4));
            } else {                                  // B tiles: 5 x 64row x 128B
                int q2 = q - 1024;
                int j = q2 >> 9, idx = q2 & 511, row = idx >> 3, c16 = idx & 7;
                size_t pb = (size_t)((j * BB + b) * HWD + p0 + row);
                if (mn) src = (const char*)(g_Xh + pb * 256 + ka + c16 * 8);
                else    src = g_X8 + pb * 512 + ka + c16 * 16;
                doff = OFF_B + j * 8192 + row * 128 + ((c16 << 4) ^ ((row & 7) << 4));
            }
            unsigned ds = (unsigned)__cvta_generic_to_shared(stg + doff);
            asm volatile("cp.async.cg.shared.global [%0], [%1], 16;"
                         :: "r"(ds), "l"(src));
        }
        asm volatile("cp.async.commit_group;");
    };

    load_chunk(0, 0);
    load_chunk(1, 1);

    int stage = 0;
    for (int c = 0; c < NCH; c++) {
        asm volatile("cp.async.wait_group 1;");
        __syncthreads();
        if (c + 2 < NCH) {
            int s2 = stage + 2; if (s2 >= NSTG) s2 -= NSTG;
            load_chunk(c + 2, s2);
        }
        const unsigned stq = smem_base + (unsigned)(stage * STG);
        const bool mn = (c < 4);

        #pragma unroll
        for (int st4 = 0; st4 < 4; st4++) {
            const int kko = st4 * 32;                 // 32B k-window in both modes
            unsigned aM[4], aW[4];
            {
                unsigned aa = stq + arow * 128 + (unsigned)((kko + a16) ^ sw7);
                LDM4(aM, aa);
                LDM4(aW, aa + OFF_AW);
            }
            unsigned bf[5][4];
            #pragma unroll
            for (int j = 0; j < NN; j++) {
                unsigned bb0 = stq + OFF_B + j * 8192 + brow * 128
                             + (unsigned)((kko + b16) ^ sw7);
                LDM4(bf[j], bb0);
            }
            if (mn) {
                #pragma unroll
                for (int j = 0; j < NN; j++) {
                    MMA32(acc[j][0], aM, bf[j][0], bf[j][1]);
                    MMA32(acc[j][1], aM, bf[j][2], bf[j][3]);
                    if (j == i) {
                        MMA32(acc[5][0], aW, bf[j][0], bf[j][1]);
                        MMA32(acc[5][1], aW, bf[j][2], bf[j][3]);
                    }
                }
            } else {
                #pragma unroll
                for (int j = 0; j < NN; j++) {
                    MMA8(accC[j][0], aM, bf[j][0], bf[j][1]);
                    MMA8(accC[j][1], aM, bf[j][2], bf[j][3]);
                    if (j == i) {
                        MMA8(accC[5][0], aW, bf[j][0], bf[j][1]);
                        MMA8(accC[5][1], aW, bf[j][2], bf[j][3]);
                    }
                }
            }
        }
        if (++stage == NSTG) stage = 0;
    }

    // ---- fused epilogue: t = main + corr*K2F + bias; edge/softmax/aggregate ----
    const int tq = lane >> 2, tr = lane & 3;
    #pragma unroll
    for (int rh = 0; rh < 2; rh++) {
        const int o = o0 + wo + rh * 8 + tq;
        const float bv = bias[i * CC + o];
        #pragma unroll
        for (int g = 0; g < 2; g++) {
            const int p = p0 + wn + g * 8 + tr * 2;
            float2 xj[NN];
            #pragma unroll
            for (int j = 0; j < NN; j++)
                xj[j] = *(const float2*)(
                    x + ((size_t)((j * BB + b) * CC + o)) * HWD + p);
            float res[2];
            #pragma unroll
            for (int e = 0; e < 2; e++) {
                const int ix = rh * 2 + e;
                const float u = acc[5][g][ix] + (float)accC[5][g][ix] * K2F + bv;
                float ed[NN], m2 = 0.f;
                #pragma unroll
                for (int j = 0; j < NN; j++) {
                    float xv = e ? xj[j].y : xj[j].x;
                    float t = acc[j][g][ix] + (float)accC[j][g][ix] * K2F + u;
                    float d = fabsf(xv - t);
                    ed[j] = (d > 0.3f) ? d : 0.f;
                    m2 = fmaxf(m2, ed[j]);
                }
                float sden = 0.f, a = 0.f;
                #pragma unroll
                for (int j = 0; j < NN; j++) {
                    float wgt = __expf(ed[j] - m2);
                    sden += wgt;
                    a = fmaf(wgt, e ? xj[j].y : xj[j].x, a);
                }
                res[e] = a / sden;
            }
            *(float2*)(out + ((size_t)((i * BB + b) * CC + o)) * HWD + p) =
                make_float2(res[0], res[1]);
        }
    }
}

extern "C" void kernel_launch(void* const* d_in, const int* in_sizes, int n_in,
                              void* d_out, int out_size) {
    const float* x    = (const float*)d_in[0];   // [5,8,256,32,32]
    const float* w    = (const float*)d_in[1];   // [5,256,512]
    const float* bias = (const float*)d_in[2];   // [5,256]
    float* out = (float*)d_out;                  // [5,8,256,32,32]

    cudaFuncSetAttribute(fused_kernel,
                         cudaFuncAttributeMaxDynamicSharedMemorySize,
                         (int)sizeof(SmemT));

    prep_w<<<(NN * CC * CC + 255) / 256, 256>>>(w);
    prep_x<<<NN * BB * 8 * 8, 256>>>(x);
    // grid: x = b(8)*ptile(16) = 128, y = o-tiles(4), z = i(5)
    fused_kernel<<<dim3(128, 4, 5), THREADS, sizeof(SmemT)>>>(x, bias, out);
}

// round 17
// speedup vs baseline: 1.9995x; 1.9709x over previous
#include <cuda_runtime.h>
#include <cuda_fp16.h>

#define NN 5
#define BB 8
#define CC 256
#define HWD 1024
#define NCH 4             // main fp16 f32acc only (k64 each)
#define TM 64
#define TPX 64
#define THREADS 512
#define NSTG 3
#define WIN 2.5e-3f       // threshold repair window

// fp16 hi operands (K=256), k-contiguous
__device__ __align__(16) __half g_Ahm[NN * CC * 256];
__device__ __align__(16) __half g_Ahw[NN * CC * 256];
__device__ __align__(16) __half g_Xh [NN * BB * HWD * 256];

__global__ void prep_w(const float* __restrict__ w) {
    int idx = blockIdx.x * blockDim.x + threadIdx.x;   // (i*CC+o)*CC + k
    if (idx >= NN * CC * CC) return;
    int k = idx & 255;
    int oi = idx >> 8;
    int o = oi & 255, i = oi >> 8;
    const float* row = w + (size_t)(i * CC + o) * (2 * CC);
    float w2 = row[CC + k];
    float m  = row[k] + w2;
    size_t bh = (size_t)(i * CC + o) * 256 + k;
    g_Ahm[bh] = __float2half_rn(m);
    g_Ahw[bh] = __float2half_rn(w2);
}

// Transpose [k][p] -> [p][k] fp16, via smem tile (32k x 128p).
__global__ __launch_bounds__(256) void prep_x(const float* __restrict__ x) {
    __shared__ float s[32][129];
    int bid = blockIdx.x;                      // jb(40) * ktile(8) * ptile(8)
    int pt = bid & 7, kt = (bid >> 3) & 7, jb = bid >> 6;
    int k0 = kt * 32, p0 = pt * 128;
    int tid = threadIdx.x;
    #pragma unroll
    for (int t = 0; t < 16; t++) {
        int idx = tid + t * 256;
        int kk = idx >> 7, pp = idx & 127;
        s[kk][pp] = x[((size_t)jb * CC + k0 + kk) * HWD + p0 + pp];
    }
    __syncthreads();
    int pp = tid & 127, kh = tid >> 7;         // which 16-k half
    __half hbuf[16];
    #pragma unroll
    for (int kk = 0; kk < 16; kk++)
        hbuf[kk] = __float2half_rn(s[kh * 16 + kk][pp]);
    __half* dh = g_Xh + ((size_t)(jb * HWD + p0 + pp)) * 256 + k0 + kh * 16;
    *(uint4*)dh       = *(uint4*)hbuf;
    *(uint4*)(dh + 8) = *(uint4*)(hbuf + 8);
}

// ---- smem stage: A_M 8K | A_W 8K | B[5] 40K = 56KB; 3 stages = 168KB ----
#define STG 57344
#define OFF_AW 8192
#define OFF_B 16384
struct SmemT { char st[NSTG][STG]; };

#define LDM4(r, a) \
    asm volatile("ldmatrix.sync.aligned.m8n8.x4.shared.b16 {%0,%1,%2,%3}, [%4];" \
        : "=r"((r)[0]), "=r"((r)[1]), "=r"((r)[2]), "=r"((r)[3]) : "r"(a))

#define MMA32(d, a, b0, b1) \
    asm volatile("mma.sync.aligned.m16n8k16.row.col.f32.f16.f16.f32 " \
        "{%0,%1,%2,%3}, {%4,%5,%6,%7}, {%8,%9}, {%0,%1,%2,%3};" \
        : "+f"((d)[0]), "+f"((d)[1]), "+f"((d)[2]), "+f"((d)[3]) \
        : "r"((a)[0]), "r"((a)[1]), "r"((a)[2]), "r"((a)[3]), "r"(b0), "r"(b1))

// Warp-cooperative exact t = W1.x_j + W2.(x_i+x_j) (no bias). All lanes return sum.
__device__ __forceinline__ float coop_t(const float* __restrict__ w,
                                        const float* __restrict__ x,
                                        int i, int b, int o, int j, int p, int lane)
{
    const float* wrow = w + (size_t)(i * CC + o) * (2 * CC);
    const float* xj = x + ((size_t)(j * BB + b) * CC) * HWD + p;
    const float* xi = x + ((size_t)(i * BB + b) * CC) * HWD + p;
    float s = 0.f;
    #pragma unroll
    for (int t = 0; t < 8; t++) {
        int k = lane + t * 32;
        float w1 = wrow[k], w2 = wrow[CC + k];
        float a = xj[(size_t)k * HWD];
        float c = xi[(size_t)k * HWD];
        s += w1 * a + w2 * (a + c);
    }
    #pragma unroll
    for (int off = 16; off; off >>= 1)
        s += __shfl_xor_sync(0xffffffffu, s, off);
    return s;
}

__global__ __launch_bounds__(THREADS, 1) void fused_kernel(
    const float* __restrict__ x,
    const float* __restrict__ w,
    const float* __restrict__ bias,
    float* __restrict__ out)
{
    extern __shared__ __align__(16) char smem_raw[];
    SmemT& sm = *reinterpret_cast<SmemT*>(smem_raw);

    const int i  = blockIdx.z;
    const int o0 = blockIdx.y * TM;
    const int b  = blockIdx.x >> 4;
    const int p0 = (blockIdx.x & 15) * TPX;

    const int tid  = threadIdx.x;
    const int lane = tid & 31;
    const int wid  = tid >> 5;
    const int wo = (wid >> 2) * 16;            // warp o offset (0,16,32,48)
    const int wn = (wid & 3) * 16;             // warp px offset (0,16,32,48)
    const unsigned smem_base = (unsigned)__cvta_generic_to_shared(&sm);

    const int sw7  = (lane & 7) << 4;
    const int arow = wo + ((lane >> 3) & 1) * 8 + (lane & 7);
    const int a16  = (lane >> 4) * 16;
    const int brow = wn + (lane >> 4) * 8 + (lane & 7);
    const int b16  = ((lane >> 3) & 1) * 16;

    float acc[6][2][4];
    #pragma unroll
    for (int m = 0; m < 6; m++)
        #pragma unroll
        for (int g = 0; g < 2; g++)
            #pragma unroll
            for (int e = 0; e < 4; e++) acc[m][g][e] = 0.f;

    auto load_chunk = [&](int c, int s) {
        char* stg = sm.st[s];
        const int ka = c * 64;
        #pragma unroll
        for (int t = 0; t < 7; t++) {
            int q = tid + t * THREADS;                // 3584 x 16B
            const char* src;
            int doff;
            if (q < 1024) {                           // A tiles: 2 mats x 64row x 128B
                int mat = q >> 9, idx = q & 511, row = idx >> 3, c16 = idx & 7;
                const __half* g = mat ? g_Ahw : g_Ahm;
                src = (const char*)(g + (size_t)(i * CC + o0 + row) * 256 + ka + c16 * 8);
                doff = mat * OFF_AW + row * 128 + ((c16 << 4) ^ ((row & 7) << 4));
            } else {                                  // B tiles: 5 x 64row x 128B
                int q2 = q - 1024;
                int j = q2 >> 9, idx = q2 & 511, row = idx >> 3, c16 = idx & 7;
                src = (const char*)(g_Xh
                    + ((size_t)((j * BB + b) * HWD + p0 + row)) * 256 + ka + c16 * 8);
                doff = OFF_B + j * 8192 + row * 128 + ((c16 << 4) ^ ((row & 7) << 4));
            }
            unsigned ds = (unsigned)__cvta_generic_to_shared(stg + doff);
            asm volatile("cp.async.cg.shared.global [%0], [%1], 16;"
                         :: "r"(ds), "l"(src));
        }
        asm volatile("cp.async.commit_group;");
    };

    load_chunk(0, 0);
    load_chunk(1, 1);

    int stage = 0;
    for (int c = 0; c < NCH; c++) {
        asm volatile("cp.async.wait_group 1;");
        __syncthreads();
        if (c + 2 < NCH) {
            int s2 = stage + 2; if (s2 >= NSTG) s2 -= NSTG;
            load_chunk(c + 2, s2);
        }
        const unsigned stq = smem_base + (unsigned)(stage * STG);

        #pragma unroll
        for (int st4 = 0; st4 < 4; st4++) {
            const int kko = st4 * 32;
            unsigned aM[4], aW[4];
            {
                unsigned aa = stq + arow * 128 + (unsigned)((kko + a16) ^ sw7);
                LDM4(aM, aa);
                LDM4(aW, aa + OFF_AW);
            }
            unsigned bf[5][4];
            #pragma unroll
            for (int j = 0; j < NN; j++) {
                unsigned bb0 = stq + OFF_B + j * 8192 + brow * 128
                             + (unsigned)((kko + b16) ^ sw7);
                LDM4(bf[j], bb0);
            }
            #pragma unroll
            for (int j = 0; j < NN; j++) {
                MMA32(acc[j][0], aM, bf[j][0], bf[j][1]);
                MMA32(acc[j][1], aM, bf[j][2], bf[j][3]);
                if (j == i) {
                    MMA32(acc[5][0], aW, bf[j][0], bf[j][1]);
                    MMA32(acc[5][1], aW, bf[j][2], bf[j][3]);
                }
            }
        }
        if (++stage == NSTG) stage = 0;
    }

    // ---- fused epilogue with threshold repair ----
    const int tq = lane >> 2, tr = lane & 3;
    #pragma unroll
    for (int rh = 0; rh < 2; rh++) {
        const int o = o0 + wo + rh * 8 + tq;
        const float bv = bias[i * CC + o];
        #pragma unroll
        for (int g = 0; g < 2; g++) {
            const int p = p0 + wn + g * 8 + tr * 2;
            float2 xj[NN];
            #pragma unroll
            for (int j = 0; j < NN; j++)
                xj[j] = *(const float2*)(
                    x + ((size_t)((j * BB + b) * CC + o)) * HWD + p);

            // d values for both e-halves, all j
            float dv[2][NN];
            #pragma unroll
            for (int e = 0; e < 2; e++) {
                const int ix = rh * 2 + e;
                const float u = acc[5][g][ix] + bv;
                #pragma unroll
                for (int j = 0; j < NN; j++) {
                    float xv = e ? xj[j].y : xj[j].x;
                    dv[e][j] = fabsf(xv - (acc[j][g][ix] + u));
                }
            }

            // repair pass: exact recompute where |d-0.3| < WIN
            #pragma unroll
            for (int e = 0; e < 2; e++) {
                #pragma unroll
                for (int j = 0; j < NN; j++) {
                    unsigned need = fabsf(dv[e][j] - 0.3f) < WIN;
                    unsigned mask = __ballot_sync(0xffffffffu, need);
                    while (mask) {
                        int src = __ffs(mask) - 1;
                        mask &= mask - 1;
                        int oo = __shfl_sync(0xffffffffu, o, src);
                        int pp = __shfl_sync(0xffffffffu, p + e, src);
                        float bs = __shfl_sync(0xffffffffu, bv, src);
                        float xv = __shfl_sync(0xffffffffu,
                                               e ? xj[j].y : xj[j].x, src);
                        float te = coop_t(w, x, i, b, oo, j, pp, lane) + bs;
                        float de = fabsf(xv - te);
                        if (lane == src) dv[e][j] = de;
                    }
                }
            }

            float res[2];
            #pragma unroll
            for (int e = 0; e < 2; e++) {
                float ed[NN], m2 = 0.f;
                #pragma unroll
                for (int j = 0; j < NN; j++) {
                    ed[j] = (dv[e][j] > 0.3f) ? dv[e][j] : 0.f;
                    m2 = fmaxf(m2, ed[j]);
                }
                float sden = 0.f, a = 0.f;
                #pragma unroll
                for (int j = 0; j < NN; j++) {
                    float wgt = __expf(ed[j] - m2);
                    sden += wgt;
                    a = fmaf(wgt, e ? xj[j].y : xj[j].x, a);
                }
                res[e] = a / sden;
            }
            *(float2*)(out + ((size_t)((i * BB + b) * CC + o)) * HWD + p) =
                make_float2(res[0], res[1]);
        }
    }
}

extern "C" void kernel_launch(void* const* d_in, const int* in_sizes, int n_in,
                              void* d_out, int out_size) {
    const float* x    = (const float*)d_in[0];   // [5,8,256,32,32]
    const float* w    = (const float*)d_in[1];   // [5,256,512]
    const float* bias = (const float*)d_in[2];   // [5,256]
    float* out = (float*)d_out;                  // [5,8,256,32,32]

    cudaFuncSetAttribute(fused_kernel,
                         cudaFuncAttributeMaxDynamicSharedMemorySize,
                         (int)sizeof(SmemT));

    prep_w<<<(NN * CC * CC + 255) / 256, 256>>>(w);
    prep_x<<<NN * BB * 8 * 8, 256>>>(x);
    // grid: x = b(8)*ptile(16) = 128, y = o-tiles(4), z = i(5)
    fused_kernel<<<dim3(128, 4, 5), THREADS, sizeof(SmemT)>>>(x, w, bias, out);
}